// round 8
// baseline (speedup 1.0000x reference)
#include <cuda_runtime.h>
#include <cuda_bf16.h>
#include <cstdint>

#define N_NODES 50000
#define DEG     32
#define DFEAT   128
#define DIN     256
#define DOUT    256

#define BM 64
#define XLD 264                  // bf16 row stride for xs (pad 8)
#define N_TILES ((N_NODES + BM - 1) / BM)   // 782
#define GRID 148
#define MAX_T ((N_TILES + GRID - 1) / GRID) // 6 produce slots -> 7 phases

// smem: [hi buf0][lo buf0][hi buf1][lo buf1]
#define XS_BUF_BYTES (2u * BM * XLD * 2u)   // hi+lo per buffer = 67584
#define SMEM_BYTES   (2u * XS_BUF_BYTES)    // 135168

// W in fragment order: [ksg(16)][nblk(32)][lane(32)] -> uint4
//   .x/.y = hi bf16x2 (k low/high half) ; .z/.w = lo bf16x2
__device__ uint4 g_wfrag[16 * 32 * 32];     // 256 KB

__device__ __forceinline__ void bf16x2_split(float x, float y,
                                             uint32_t& hi, uint32_t& lo) {
    __nv_bfloat162 h = __float22bfloat162_rn(make_float2(x, y));
    float2 hf = __bfloat1622float2(h);
    __nv_bfloat162 l = __float22bfloat162_rn(make_float2(x - hf.x, y - hf.y));
    hi = *reinterpret_cast<uint32_t*>(&h);
    lo = *reinterpret_cast<uint32_t*>(&l);
}

__device__ __forceinline__ void mma_bf16(float* d, const uint32_t* a,
                                         uint32_t b0, uint32_t b1) {
    asm volatile(
        "mma.sync.aligned.m16n8k16.row.col.f32.bf16.bf16.f32 "
        "{%0,%1,%2,%3}, {%4,%5,%6,%7}, {%8,%9}, {%0,%1,%2,%3};"
        : "+f"(d[0]), "+f"(d[1]), "+f"(d[2]), "+f"(d[3])
        : "r"(a[0]), "r"(a[1]), "r"(a[2]), "r"(a[3]),
          "r"(b0), "r"(b1));
}

// ------------- prologue: split W into fragment-ordered uint4 ---------------
__global__ void wsplit_kernel(const float* __restrict__ W) {
    const int idx = blockIdx.x * blockDim.x + threadIdx.x;   // 16384
    const int lane = idx & 31;
    const int nblk = (idx >> 5) & 31;
    const int ksg  = idx >> 10;            // 0..15
    const int g = lane >> 2, t = lane & 3;
    const int n  = nblk * 8 + g;
    const int k0 = ksg * 16 + 2 * t;
    const int k1 = k0 + 8;

    uint4 v;
    bf16x2_split(W[k0 * DOUT + n], W[(k0 + 1) * DOUT + n], v.x, v.z);
    bf16x2_split(W[k1 * DOUT + n], W[(k1 + 1) * DOUT + n], v.y, v.w);
    g_wfrag[idx] = v;
}

// ------------------- producer: gather one tile into buffer -----------------
__device__ __forceinline__ void produce_tile(const float* __restrict__ features,
                                             const int* __restrict__ edges,
                                             uint32_t* xs_hi, uint32_t* xs_lo,
                                             int node0, int pwid, int lane)
{
    #pragma unroll
    for (int s = 0; s < BM / 8; s++) {
        const int m = pwid * (BM / 8) + s;
        const int node = node0 + m;
        const int wbase = m * (XLD / 2) + lane * 2;
        if (node < N_NODES) {
            const int my_e = edges[node * DEG + lane];
            const float4 self = *reinterpret_cast<const float4*>(
                features + (long long)node * DFEAT + lane * 4);

            float4 acc = make_float4(0.f, 0.f, 0.f, 0.f);
            #pragma unroll
            for (int j = 0; j < DEG; j++) {
                const int idx = __shfl_sync(0xffffffffu, my_e, j);
                const float4 v = *reinterpret_cast<const float4*>(
                    features + (long long)idx * DFEAT + lane * 4);
                acc.x += v.x; acc.y += v.y; acc.z += v.z; acc.w += v.w;
            }
            const float inv = 1.0f / (float)DEG;
            acc.x *= inv; acc.y *= inv; acc.z *= inv; acc.w *= inv;

            uint32_t h0, l0, h1, l1;
            bf16x2_split(self.x, self.y, h0, l0);
            bf16x2_split(self.z, self.w, h1, l1);
            xs_hi[wbase]     = h0;  xs_hi[wbase + 1] = h1;
            xs_lo[wbase]     = l0;  xs_lo[wbase + 1] = l1;

            bf16x2_split(acc.x, acc.y, h0, l0);
            bf16x2_split(acc.z, acc.w, h1, l1);
            xs_hi[wbase + 64] = h0; xs_hi[wbase + 65] = h1;
            xs_lo[wbase + 64] = l0; xs_lo[wbase + 65] = l1;
        } else {
            xs_hi[wbase] = 0u;      xs_hi[wbase + 1] = 0u;
            xs_lo[wbase] = 0u;      xs_lo[wbase + 1] = 0u;
            xs_hi[wbase + 64] = 0u; xs_hi[wbase + 65] = 0u;
            xs_lo[wbase + 64] = 0u; xs_lo[wbase + 65] = 0u;
        }
    }
}

// ------------------- consumer: GEMM one tile from buffer -------------------
__device__ __forceinline__ void consume_tile(const uint32_t* xs_hi,
                                             const uint32_t* xs_lo,
                                             float* __restrict__ out,
                                             int node0, int cwid, int lane)
{
    const int wm = cwid & 1;
    const int wn = cwid >> 1;               // 0..3
    const int g  = lane >> 2;
    const int t  = lane & 3;
    const int m_base = wm * 32;
    const int n_base = wn * 64;

    float acc[2][8][4];
    #pragma unroll
    for (int mt = 0; mt < 2; mt++)
        #pragma unroll
        for (int nt = 0; nt < 8; nt++)
            #pragma unroll
            for (int r = 0; r < 4; r++)
                acc[mt][nt][r] = 0.f;

    const uint4* wbase_p = g_wfrag + (wn * 8) * 32 + lane;

    #pragma unroll 2
    for (int ksg = 0; ksg < 16; ksg++) {
        uint32_t ah[2][4], al[2][4];
        #pragma unroll
        for (int mt = 0; mt < 2; mt++) {
            const int r0 = m_base + mt * 16 + g;
            const int i00 = r0 * (XLD / 2) + ksg * 8 + t;
            const int i01 = (r0 + 8) * (XLD / 2) + ksg * 8 + t;
            ah[mt][0] = xs_hi[i00];     al[mt][0] = xs_lo[i00];
            ah[mt][1] = xs_hi[i01];     al[mt][1] = xs_lo[i01];
            ah[mt][2] = xs_hi[i00 + 4]; al[mt][2] = xs_lo[i00 + 4];
            ah[mt][3] = xs_hi[i01 + 4]; al[mt][3] = xs_lo[i01 + 4];
        }

        #pragma unroll
        for (int h = 0; h < 2; h++) {
            uint4 bw[4];
            #pragma unroll
            for (int q = 0; q < 4; q++)
                bw[q] = wbase_p[(ksg * 32 + h * 4 + q) * 32];

            #pragma unroll
            for (int q = 0; q < 4; q++) {
                const int nt = h * 4 + q;
                #pragma unroll
                for (int mt = 0; mt < 2; mt++) {
                    mma_bf16(acc[mt][nt], ah[mt], bw[q].x, bw[q].y);  // Ah*Bh
                    mma_bf16(acc[mt][nt], al[mt], bw[q].x, bw[q].y);  // Al*Bh
                    mma_bf16(acc[mt][nt], ah[mt], bw[q].z, bw[q].w);  // Ah*Bl
                }
            }
        }
    }

    #pragma unroll
    for (int mt = 0; mt < 2; mt++) {
        const int r0 = node0 + m_base + mt * 16 + g;
        #pragma unroll
        for (int nt = 0; nt < 8; nt++) {
            const int c0 = n_base + nt * 8 + t * 2;
            if (r0 < N_NODES) {
                float2 v0 = make_float2(fmaxf(acc[mt][nt][0], 0.f),
                                        fmaxf(acc[mt][nt][1], 0.f));
                *reinterpret_cast<float2*>(out + (long long)r0 * DOUT + c0) = v0;
            }
            if (r0 + 8 < N_NODES) {
                float2 v1 = make_float2(fmaxf(acc[mt][nt][2], 0.f),
                                        fmaxf(acc[mt][nt][3], 0.f));
                *reinterpret_cast<float2*>(out + (long long)(r0 + 8) * DOUT + c0) = v1;
            }
        }
    }
}

// --------------- persistent warp-specialized pipelined kernel --------------
__global__ __launch_bounds__(512, 1)
void sage_ws_kernel(const float* __restrict__ features,
                    const int* __restrict__ edges,
                    float* __restrict__ out)
{
    extern __shared__ char sm[];
    const int tid  = threadIdx.x;
    const int lane = tid & 31;
    const int wid  = tid >> 5;              // 0..15
    const bool is_producer = (wid < 8);

    for (int t = 0; t <= MAX_T; t++) {
        if (is_producer) {
            const int tile = blockIdx.x + t * GRID;
            if (t < MAX_T && tile < N_TILES) {
                const int buf = t & 1;
                uint32_t* xs_hi = reinterpret_cast<uint32_t*>(sm + buf * XS_BUF_BYTES);
                uint32_t* xs_lo = xs_hi + BM * XLD / 2;
                produce_tile(features, edges, xs_hi, xs_lo, tile * BM, wid, lane);
            }
        } else {
            const int tile = blockIdx.x + (t - 1) * GRID;
            if (t >= 1 && tile < N_TILES) {
                const int buf = (t - 1) & 1;
                const uint32_t* xs_hi = reinterpret_cast<const uint32_t*>(sm + buf * XS_BUF_BYTES);
                const uint32_t* xs_lo = xs_hi + BM * XLD / 2;
                consume_tile(xs_hi, xs_lo, out, tile * BM, wid - 8, lane);
            }
        }
        __syncthreads();
    }
}

// ------------------------------- launcher ----------------------------------
extern "C" void kernel_launch(void* const* d_in, const int* in_sizes, int n_in,
                              void* d_out, int out_size)
{
    const float* features = (const float*)d_in[0];
    const int*   edges    = (const int*)d_in[1];
    const float* kernel   = (const float*)d_in[2];
    float*       out      = (float*)d_out;
    (void)in_sizes; (void)n_in; (void)out_size;

    static bool attr_set = false;
    if (!attr_set) {
        cudaFuncSetAttribute(sage_ws_kernel,
                             cudaFuncAttributeMaxDynamicSharedMemorySize, SMEM_BYTES);
        attr_set = true;
    }

    wsplit_kernel<<<64, 256>>>(kernel);
    sage_ws_kernel<<<GRID, 512, SMEM_BYTES>>>(features, edges, out);
}

// round 9
// speedup vs baseline: 1.1048x; 1.1048x over previous
#include <cuda_runtime.h>
#include <cuda_bf16.h>
#include <cstdint>

#define N_NODES 50000
#define DEG     32
#define DFEAT   128
#define DIN     256
#define DOUT    256

#define BM 64
#define XLD 264          // bf16 row stride for xs (pad 8)

// smem: xs hi + lo only
#define XS_HI_OFF 0u
#define XS_LO_OFF (BM * XLD * 2u)            // 33792
#define SMEM_BYTES (2u * BM * XLD * 2u)      // 67584

// W in fragment order: [ksg(16)][nblk(32)][lane(32)] -> uint4
//   .x/.y = hi bf16x2 (k low/high half of ksg) ; .z/.w = lo bf16x2
__device__ uint4 g_wfrag[16 * 32 * 32];      // 256 KB

__device__ __forceinline__ void bf16x2_split(float x, float y,
                                             uint32_t& hi, uint32_t& lo) {
    __nv_bfloat162 h = __float22bfloat162_rn(make_float2(x, y));
    float2 hf = __bfloat1622float2(h);
    __nv_bfloat162 l = __float22bfloat162_rn(make_float2(x - hf.x, y - hf.y));
    hi = *reinterpret_cast<uint32_t*>(&h);
    lo = *reinterpret_cast<uint32_t*>(&l);
}

__device__ __forceinline__ void mma_bf16(float* d, const uint32_t* a,
                                         uint32_t b0, uint32_t b1) {
    asm volatile(
        "mma.sync.aligned.m16n8k16.row.col.f32.bf16.bf16.f32 "
        "{%0,%1,%2,%3}, {%4,%5,%6,%7}, {%8,%9}, {%0,%1,%2,%3};"
        : "+f"(d[0]), "+f"(d[1]), "+f"(d[2]), "+f"(d[3])
        : "r"(a[0]), "r"(a[1]), "r"(a[2]), "r"(a[3]),
          "r"(b0), "r"(b1));
}

// ------------- prologue: split W into fragment-ordered uint4 ---------------
__global__ void wsplit_kernel(const float* __restrict__ W) {
    const int idx = blockIdx.x * blockDim.x + threadIdx.x;   // 16384
    const int lane = idx & 31;
    const int nblk = (idx >> 5) & 31;
    const int ksg  = idx >> 10;            // 0..15
    const int g = lane >> 2, t = lane & 3;
    const int n  = nblk * 8 + g;
    const int k0 = ksg * 16 + 2 * t;
    const int k1 = k0 + 8;

    uint4 v;
    bf16x2_split(W[k0 * DOUT + n], W[(k0 + 1) * DOUT + n], v.x, v.z);
    bf16x2_split(W[k1 * DOUT + n], W[(k1 + 1) * DOUT + n], v.y, v.w);
    g_wfrag[idx] = v;
}

// ------------------------------ fused kernel -------------------------------
__global__ __launch_bounds__(256, 2)
void sage_fused_kernel(const float* __restrict__ features,
                       const int* __restrict__ edges,
                       float* __restrict__ out)
{
    extern __shared__ char sm[];
    uint32_t* xs_hi = reinterpret_cast<uint32_t*>(sm + XS_HI_OFF);
    uint32_t* xs_lo = reinterpret_cast<uint32_t*>(sm + XS_LO_OFF);

    const int tid  = threadIdx.x;
    const int lane = tid & 31;
    const int wid  = tid >> 5;            // 0..7
    const int node0 = blockIdx.x * BM;

    // ---------------- Phase 1: gather + mean + split to bf16 smem ----------
    #pragma unroll
    for (int s = 0; s < BM / 8; s++) {
        const int m = wid * (BM / 8) + s;
        const int node = node0 + m;
        const int wbase = m * (XLD / 2) + lane * 2;
        if (node < N_NODES) {
            const int my_e = edges[node * DEG + lane];
            const float4 self = *reinterpret_cast<const float4*>(
                features + (long long)node * DFEAT + lane * 4);

            float4 acc = make_float4(0.f, 0.f, 0.f, 0.f);
            #pragma unroll
            for (int j = 0; j < DEG; j++) {
                const int idx = __shfl_sync(0xffffffffu, my_e, j);
                const float4 v = *reinterpret_cast<const float4*>(
                    features + (long long)idx * DFEAT + lane * 4);
                acc.x += v.x; acc.y += v.y; acc.z += v.z; acc.w += v.w;
            }
            const float inv = 1.0f / (float)DEG;
            acc.x *= inv; acc.y *= inv; acc.z *= inv; acc.w *= inv;

            uint32_t h0, l0, h1, l1;
            bf16x2_split(self.x, self.y, h0, l0);
            bf16x2_split(self.z, self.w, h1, l1);
            xs_hi[wbase]     = h0;  xs_hi[wbase + 1] = h1;
            xs_lo[wbase]     = l0;  xs_lo[wbase + 1] = l1;

            bf16x2_split(acc.x, acc.y, h0, l0);
            bf16x2_split(acc.z, acc.w, h1, l1);
            xs_hi[wbase + 64] = h0; xs_hi[wbase + 65] = h1;
            xs_lo[wbase + 64] = l0; xs_lo[wbase + 65] = l1;
        } else {
            xs_hi[wbase] = 0u;      xs_hi[wbase + 1] = 0u;
            xs_lo[wbase] = 0u;      xs_lo[wbase + 1] = 0u;
            xs_hi[wbase + 64] = 0u; xs_hi[wbase + 65] = 0u;
            xs_lo[wbase + 64] = 0u; xs_lo[wbase + 65] = 0u;
        }
    }
    __syncthreads();

    // ---------------- Phase 2: bf16x3 GEMM, B direct from L2 ---------------
    // 8 warps, each owns FULL M=64 x 32 N-cols (mt=4, nt=4) -> every B
    // fragment is read by exactly one warp (B LDG halved vs 2xM tiling).
    const int g  = lane >> 2;
    const int t  = lane & 3;
    const int n_base = wid * 32;

    float acc[4][4][4];
    #pragma unroll
    for (int mt = 0; mt < 4; mt++)
        #pragma unroll
        for (int nt = 0; nt < 4; nt++)
            #pragma unroll
            for (int r = 0; r < 4; r++)
                acc[mt][nt][r] = 0.f;

    // nblk = wid*4 + nt
    const uint4* wbase_p = g_wfrag + (wid * 4) * 32 + lane;

    #pragma unroll 2
    for (int ksg = 0; ksg < 16; ksg++) {
        // B fragments for this warp's 4 n-blocks (single reader per fragment)
        uint4 bw[4];
        #pragma unroll
        for (int q = 0; q < 4; q++)
            bw[q] = wbase_p[(ksg * 32 + q) * 32];

        // A fragments: full M=64
        uint32_t ah[4][4], al[4][4];
        #pragma unroll
        for (int mt = 0; mt < 4; mt++) {
            const int r0 = mt * 16 + g;
            const int i00 = r0 * (XLD / 2) + ksg * 8 + t;
            const int i01 = (r0 + 8) * (XLD / 2) + ksg * 8 + t;
            ah[mt][0] = xs_hi[i00];     al[mt][0] = xs_lo[i00];
            ah[mt][1] = xs_hi[i01];     al[mt][1] = xs_lo[i01];
            ah[mt][2] = xs_hi[i00 + 4]; al[mt][2] = xs_lo[i00 + 4];
            ah[mt][3] = xs_hi[i01 + 4]; al[mt][3] = xs_lo[i01 + 4];
        }

        #pragma unroll
        for (int nt = 0; nt < 4; nt++) {
            #pragma unroll
            for (int mt = 0; mt < 4; mt++) {
                mma_bf16(acc[mt][nt], ah[mt], bw[nt].x, bw[nt].y);  // Ah*Bh
                mma_bf16(acc[mt][nt], al[mt], bw[nt].x, bw[nt].y);  // Al*Bh
                mma_bf16(acc[mt][nt], ah[mt], bw[nt].z, bw[nt].w);  // Ah*Bl
            }
        }
    }

    // ---------------- Phase 3: ReLU + store from registers -----------------
    #pragma unroll
    for (int mt = 0; mt < 4; mt++) {
        const int r0 = node0 + mt * 16 + g;
        #pragma unroll
        for (int nt = 0; nt < 4; nt++) {
            const int c0 = n_base + nt * 8 + t * 2;
            if (r0 < N_NODES) {
                float2 v0 = make_float2(fmaxf(acc[mt][nt][0], 0.f),
                                        fmaxf(acc[mt][nt][1], 0.f));
                *reinterpret_cast<float2*>(out + (long long)r0 * DOUT + c0) = v0;
            }
            if (r0 + 8 < N_NODES) {
                float2 v1 = make_float2(fmaxf(acc[mt][nt][2], 0.f),
                                        fmaxf(acc[mt][nt][3], 0.f));
                *reinterpret_cast<float2*>(out + (long long)(r0 + 8) * DOUT + c0) = v1;
            }
        }
    }
}

extern "C" void kernel_launch(void* const* d_in, const int* in_sizes, int n_in,
                              void* d_out, int out_size)
{
    const float* features = (const float*)d_in[0];
    const int*   edges    = (const int*)d_in[1];
    const float* kernel   = (const float*)d_in[2];
    float*       out      = (float*)d_out;
    (void)in_sizes; (void)n_in; (void)out_size;

    static bool attr_set = false;
    if (!attr_set) {
        cudaFuncSetAttribute(sage_fused_kernel,
                             cudaFuncAttributeMaxDynamicSharedMemorySize, SMEM_BYTES);
        attr_set = true;
    }

    wsplit_kernel<<<64, 256>>>(kernel);
    const int grid = (N_NODES + BM - 1) / BM;   // 782
    sage_fused_kernel<<<grid, 256, SMEM_BYTES>>>(features, edges, out);
}

// round 10
// speedup vs baseline: 1.2123x; 1.0973x over previous
#include <cuda_runtime.h>
#include <cuda_bf16.h>
#include <cstdint>

#define N_NODES 50000
#define DEG     32
#define DFEAT   128
#define DIN     256
#define DOUT    256

#define BM 32
#define XLD 264          // bf16 row stride for xs (pad 8)

// smem: xs hi + lo
#define XS_HI_OFF 0u
#define XS_LO_OFF (BM * XLD * 2u)            // 16896
#define SMEM_BYTES (2u * BM * XLD * 2u)      // 33792

// W in fragment order: [ksg(16)][nblk(32)][lane(32)] -> uint4
//   .x/.y = hi bf16x2 (k low/high half of ksg) ; .z/.w = lo bf16x2
__device__ uint4 g_wfrag[16 * 32 * 32];      // 256 KB

__device__ __forceinline__ void bf16x2_split(float x, float y,
                                             uint32_t& hi, uint32_t& lo) {
    __nv_bfloat162 h = __float22bfloat162_rn(make_float2(x, y));
    float2 hf = __bfloat1622float2(h);
    __nv_bfloat162 l = __float22bfloat162_rn(make_float2(x - hf.x, y - hf.y));
    hi = *reinterpret_cast<uint32_t*>(&h);
    lo = *reinterpret_cast<uint32_t*>(&l);
}

__device__ __forceinline__ void mma_bf16(float* d, const uint32_t* a,
                                         uint32_t b0, uint32_t b1) {
    asm volatile(
        "mma.sync.aligned.m16n8k16.row.col.f32.bf16.bf16.f32 "
        "{%0,%1,%2,%3}, {%4,%5,%6,%7}, {%8,%9}, {%0,%1,%2,%3};"
        : "+f"(d[0]), "+f"(d[1]), "+f"(d[2]), "+f"(d[3])
        : "r"(a[0]), "r"(a[1]), "r"(a[2]), "r"(a[3]),
          "r"(b0), "r"(b1));
}

// ------------- prologue: split W into fragment-ordered uint4 ---------------
__global__ void wsplit_kernel(const float* __restrict__ W) {
    const int idx = blockIdx.x * blockDim.x + threadIdx.x;   // 16384
    const int lane = idx & 31;
    const int nblk = (idx >> 5) & 31;
    const int ksg  = idx >> 10;            // 0..15
    const int g = lane >> 2, t = lane & 3;
    const int n  = nblk * 8 + g;
    const int k0 = ksg * 16 + 2 * t;
    const int k1 = k0 + 8;

    uint4 v;
    bf16x2_split(W[k0 * DOUT + n], W[(k0 + 1) * DOUT + n], v.x, v.z);
    bf16x2_split(W[k1 * DOUT + n], W[(k1 + 1) * DOUT + n], v.y, v.w);
    g_wfrag[idx] = v;
}

// ------------------------------ fused kernel -------------------------------
__global__ __launch_bounds__(256, 3)
void sage_fused_kernel(const float* __restrict__ features,
                       const int* __restrict__ edges,
                       float* __restrict__ out)
{
    extern __shared__ char sm[];
    uint32_t* xs_hi = reinterpret_cast<uint32_t*>(sm + XS_HI_OFF);
    uint32_t* xs_lo = reinterpret_cast<uint32_t*>(sm + XS_LO_OFF);

    const int tid  = threadIdx.x;
    const int lane = tid & 31;
    const int wid  = tid >> 5;            // 0..7
    const int node0 = blockIdx.x * BM;

    // ---------------- Phase 1: gather + mean + split to bf16 smem ----------
    // 8 warps x 4 nodes each
    #pragma unroll
    for (int s = 0; s < BM / 8; s++) {
        const int m = wid * (BM / 8) + s;
        const int node = node0 + m;
        const int wbase = m * (XLD / 2) + lane * 2;
        if (node < N_NODES) {
            const int my_e = edges[node * DEG + lane];
            const float4 self = *reinterpret_cast<const float4*>(
                features + (long long)node * DFEAT + lane * 4);

            float4 acc = make_float4(0.f, 0.f, 0.f, 0.f);
            #pragma unroll
            for (int j = 0; j < DEG; j++) {
                const int idx = __shfl_sync(0xffffffffu, my_e, j);
                const float4 v = *reinterpret_cast<const float4*>(
                    features + (long long)idx * DFEAT + lane * 4);
                acc.x += v.x; acc.y += v.y; acc.z += v.z; acc.w += v.w;
            }
            const float inv = 1.0f / (float)DEG;
            acc.x *= inv; acc.y *= inv; acc.z *= inv; acc.w *= inv;

            uint32_t h0, l0, h1, l1;
            bf16x2_split(self.x, self.y, h0, l0);
            bf16x2_split(self.z, self.w, h1, l1);
            xs_hi[wbase]     = h0;  xs_hi[wbase + 1] = h1;
            xs_lo[wbase]     = l0;  xs_lo[wbase + 1] = l1;

            bf16x2_split(acc.x, acc.y, h0, l0);
            bf16x2_split(acc.z, acc.w, h1, l1);
            xs_hi[wbase + 64] = h0; xs_hi[wbase + 65] = h1;
            xs_lo[wbase + 64] = l0; xs_lo[wbase + 65] = l1;
        } else {
            xs_hi[wbase] = 0u;      xs_hi[wbase + 1] = 0u;
            xs_lo[wbase] = 0u;      xs_lo[wbase + 1] = 0u;
            xs_hi[wbase + 64] = 0u; xs_hi[wbase + 65] = 0u;
            xs_lo[wbase + 64] = 0u; xs_lo[wbase + 65] = 0u;
        }
    }
    __syncthreads();

    // ---------------- Phase 2: bf16x3 GEMM, B direct from L2 ---------------
    // 8 warps, each owns M=32 x 32 N-cols (mt=2, nt=4); one reader per B frag.
    const int g  = lane >> 2;
    const int t  = lane & 3;
    const int n_base = wid * 32;

    float acc[2][4][4];
    #pragma unroll
    for (int mt = 0; mt < 2; mt++)
        #pragma unroll
        for (int nt = 0; nt < 4; nt++)
            #pragma unroll
            for (int r = 0; r < 4; r++)
                acc[mt][nt][r] = 0.f;

    // nblk = wid*4 + nt
    const uint4* wbase_p = g_wfrag + (wid * 4) * 32 + lane;

    #pragma unroll 2
    for (int ksg = 0; ksg < 16; ksg++) {
        // B fragments for this warp's 4 n-blocks
        uint4 bw[4];
        #pragma unroll
        for (int q = 0; q < 4; q++)
            bw[q] = wbase_p[(ksg * 32 + q) * 32];

        // A fragments: M=32
        uint32_t ah[2][4], al[2][4];
        #pragma unroll
        for (int mt = 0; mt < 2; mt++) {
            const int r0 = mt * 16 + g;
            const int i00 = r0 * (XLD / 2) + ksg * 8 + t;
            const int i01 = (r0 + 8) * (XLD / 2) + ksg * 8 + t;
            ah[mt][0] = xs_hi[i00];     al[mt][0] = xs_lo[i00];
            ah[mt][1] = xs_hi[i01];     al[mt][1] = xs_lo[i01];
            ah[mt][2] = xs_hi[i00 + 4]; al[mt][2] = xs_lo[i00 + 4];
            ah[mt][3] = xs_hi[i01 + 4]; al[mt][3] = xs_lo[i01 + 4];
        }

        #pragma unroll
        for (int nt = 0; nt < 4; nt++) {
            #pragma unroll
            for (int mt = 0; mt < 2; mt++) {
                mma_bf16(acc[mt][nt], ah[mt], bw[nt].x, bw[nt].y);  // Ah*Bh
                mma_bf16(acc[mt][nt], al[mt], bw[nt].x, bw[nt].y);  // Al*Bh
                mma_bf16(acc[mt][nt], ah[mt], bw[nt].z, bw[nt].w);  // Ah*Bl
            }
        }
    }

    // ---------------- Phase 3: ReLU + store from registers -----------------
    #pragma unroll
    for (int mt = 0; mt < 2; mt++) {
        const int r0 = node0 + mt * 16 + g;
        #pragma unroll
        for (int nt = 0; nt < 4; nt++) {
            const int c0 = n_base + nt * 8 + t * 2;
            if (r0 < N_NODES) {
                float2 v0 = make_float2(fmaxf(acc[mt][nt][0], 0.f),
                                        fmaxf(acc[mt][nt][1], 0.f));
                *reinterpret_cast<float2*>(out + (long long)r0 * DOUT + c0) = v0;
            }
            if (r0 + 8 < N_NODES) {
                float2 v1 = make_float2(fmaxf(acc[mt][nt][2], 0.f),
                                        fmaxf(acc[mt][nt][3], 0.f));
                *reinterpret_cast<float2*>(out + (long long)(r0 + 8) * DOUT + c0) = v1;
            }
        }
    }
}

extern "C" void kernel_launch(void* const* d_in, const int* in_sizes, int n_in,
                              void* d_out, int out_size)
{
    const float* features = (const float*)d_in[0];
    const int*   edges    = (const int*)d_in[1];
    const float* kernel   = (const float*)d_in[2];
    float*       out      = (float*)d_out;
    (void)in_sizes; (void)n_in; (void)out_size;

    static bool attr_set = false;
    if (!attr_set) {
        cudaFuncSetAttribute(sage_fused_kernel,
                             cudaFuncAttributeMaxDynamicSharedMemorySize, SMEM_BYTES);
        attr_set = true;
    }

    wsplit_kernel<<<64, 256>>>(kernel);
    const int grid = (N_NODES + BM - 1) / BM;   // 1563
    sage_fused_kernel<<<grid, 256, SMEM_BYTES>>>(features, edges, out);
}